// round 1
// baseline (speedup 1.0000x reference)
#include <cuda_runtime.h>
#include <cuda_bf16.h>
#include <math.h>

// Problem constants
#define Ld 4
#define Nn 2048
#define DIN 1024
#define Hh 8
#define DHd 64
#define INNER 512
#define DOUT 1024
#define SCALEF 0.125f   // 64^-0.5

// Scratch (device globals; no allocations allowed)
__device__ float g_q[Ld*Hh*Nn*DHd];    // [L,H,N,DH]
__device__ float g_k[Ld*Hh*Nn*DHd];
__device__ float g_v[Ld*Hh*Nn*DHd];
__device__ float g_ao[Ld*Nn*INNER];    // [L,N,H*DH]
__device__ float g_mask[Ld*Nn];        // normalized 0/1 float

// ---------------------------------------------------------------------------
// Mask dtype detection + normalization.
// mask is boolean [L,N]=8192 elements; harness may deliver it as int8, int32,
// or float32. Scan the first 8192 bytes (valid for all layouts) to classify,
// then normalize to float 0/1. Deterministic.
// ---------------------------------------------------------------------------
__global__ void mask_convert_kernel(const unsigned char* __restrict__ raw) {
    __shared__ int flag_float, flag_big;
    int tid = threadIdx.x;
    if (tid == 0) { flag_float = 0; flag_big = 0; }
    __syncthreads();
    const unsigned int* w = (const unsigned int*)raw;
    for (int i = tid; i < 2048; i += blockDim.x) {   // first 8192 bytes only
        unsigned int v = w[i];
        if (v == 0x3F800000u) atomicOr(&flag_float, 1);
        else if (v > 1u)      atomicOr(&flag_big, 1);
    }
    __syncthreads();
    bool isfloat = (flag_float != 0);
    bool isbyte  = (!isfloat) && (flag_big != 0);
    for (int i = tid; i < Ld*Nn; i += blockDim.x) {
        unsigned int v;
        if (isbyte) v = raw[i];
        else        v = ((const unsigned int*)raw)[i];
        g_mask[i] = (v != 0u) ? 1.0f : 0.0f;
    }
}

// ---------------------------------------------------------------------------
// Fused QKV projection: Y[m,e] = sum_d x[m,d] * W[e,d]
// M = L*N = 8192, K = 1024, E = 512. blockIdx.z selects (Wq,Wk,Wv).
// Output written head-split: [L,H,N,DH].
// 64x64 tile, BK=16, 16x16 threads, 4x4 per thread.
// ---------------------------------------------------------------------------
__global__ __launch_bounds__(256)
void qkv_kernel(const float* __restrict__ x,
                const float* __restrict__ Wq,
                const float* __restrict__ Wk,
                const float* __restrict__ Wv) {
    const int which = blockIdx.z;
    const float* __restrict__ W = (which == 0) ? Wq : ((which == 1) ? Wk : Wv);
    float* __restrict__ outb    = (which == 0) ? g_q : ((which == 1) ? g_k : g_v);

    __shared__ float As[16][65];
    __shared__ float Bs[16][65];

    const int m0 = blockIdx.y * 64;
    const int e0 = blockIdx.x * 64;
    const int tx = threadIdx.x, ty = threadIdx.y;
    const int tid = ty * 16 + tx;
    const int lr = tid >> 2;           // 0..63 tile row
    const int lk = (tid & 3) * 4;      // 0,4,8,12

    float acc[4][4] = {};

    for (int k0 = 0; k0 < DIN; k0 += 16) {
        float4 a = *(const float4*)&x[(size_t)(m0 + lr) * DIN + k0 + lk];
        float4 b = *(const float4*)&W[(size_t)(e0 + lr) * DIN + k0 + lk];
        As[lk+0][lr] = a.x; As[lk+1][lr] = a.y; As[lk+2][lr] = a.z; As[lk+3][lr] = a.w;
        Bs[lk+0][lr] = b.x; Bs[lk+1][lr] = b.y; Bs[lk+2][lr] = b.z; Bs[lk+3][lr] = b.w;
        __syncthreads();
        #pragma unroll
        for (int kk = 0; kk < 16; kk++) {
            float ra[4], rb[4];
            #pragma unroll
            for (int i = 0; i < 4; i++) ra[i] = As[kk][ty*4 + i];
            #pragma unroll
            for (int j = 0; j < 4; j++) rb[j] = Bs[kk][tx*4 + j];
            #pragma unroll
            for (int i = 0; i < 4; i++)
                #pragma unroll
                for (int j = 0; j < 4; j++) acc[i][j] += ra[i] * rb[j];
        }
        __syncthreads();
    }

    // e-tile is exactly one head (DH=64)
    const int h = e0 / DHd;
    #pragma unroll
    for (int i = 0; i < 4; i++) {
        int m = m0 + ty*4 + i;
        int l = m / Nn, n = m % Nn;
        float* dst = &outb[(size_t)(((l*Hh + h)*Nn) + n) * DHd];
        #pragma unroll
        for (int j = 0; j < 4; j++) {
            int d = tx*4 + j;
            dst[d] = acc[i][j];
        }
    }
}

// ---------------------------------------------------------------------------
// Flash attention per (l, h): 64-query block, 64-key tiles, online softmax.
// ---------------------------------------------------------------------------
struct AttnSmem {
    float Qs[64][65];
    float Ks[64][65];
    float Vs[64][65];
    float Ps[64][65];
    float red[64][16];
    float row_m[64];
    float row_l[64];
    float row_scale[64];
    float kvalid[64];
};

__global__ __launch_bounds__(256)
void attn_kernel() {
    extern __shared__ char sbuf[];
    AttnSmem& s = *(AttnSmem*)sbuf;

    const int qb = blockIdx.x;   // 0..31
    const int h  = blockIdx.y;   // 0..7
    const int l  = blockIdx.z;   // 0..3
    const int tid = threadIdx.x;
    const int tx = tid & 15, ty = tid >> 4;
    const int q0 = qb * 64;

    const float* __restrict__ Q = g_q + (size_t)((l*Hh + h) * Nn) * DHd;
    const float* __restrict__ K = g_k + (size_t)((l*Hh + h) * Nn) * DHd;
    const float* __restrict__ V = g_v + (size_t)((l*Hh + h) * Nn) * DHd;

    // Load Q tile (64x64)
    for (int t = tid; t < 64*16; t += 256) {
        int r = t >> 4, c4 = (t & 15) * 4;
        float4 v = *(const float4*)&Q[(size_t)(q0 + r) * DHd + c4];
        s.Qs[r][c4+0] = v.x; s.Qs[r][c4+1] = v.y; s.Qs[r][c4+2] = v.z; s.Qs[r][c4+3] = v.w;
    }
    if (tid < 64) { s.row_m[tid] = -1e30f; s.row_l[tid] = 0.0f; }

    float accO[4][4] = {};

    for (int kb = 0; kb < Nn/64; kb++) {
        __syncthreads();  // protects Ks/Vs/kvalid/red reuse
        for (int t = tid; t < 64*16; t += 256) {
            int r = t >> 4, c4 = (t & 15) * 4;
            float4 kv = *(const float4*)&K[(size_t)(kb*64 + r) * DHd + c4];
            s.Ks[r][c4+0] = kv.x; s.Ks[r][c4+1] = kv.y; s.Ks[r][c4+2] = kv.z; s.Ks[r][c4+3] = kv.w;
            float4 vv = *(const float4*)&V[(size_t)(kb*64 + r) * DHd + c4];
            s.Vs[r][c4+0] = vv.x; s.Vs[r][c4+1] = vv.y; s.Vs[r][c4+2] = vv.z; s.Vs[r][c4+3] = vv.w;
        }
        if (tid < 64) s.kvalid[tid] = g_mask[l*Nn + kb*64 + tid];
        __syncthreads();

        // S = Q K^T (4x4 per thread)
        float sv[4][4] = {};
        #pragma unroll 8
        for (int d = 0; d < DHd; d++) {
            float ra[4], rb[4];
            #pragma unroll
            for (int i = 0; i < 4; i++) ra[i] = s.Qs[ty*4 + i][d];
            #pragma unroll
            for (int j = 0; j < 4; j++) rb[j] = s.Ks[tx*4 + j][d];
            #pragma unroll
            for (int i = 0; i < 4; i++)
                #pragma unroll
                for (int j = 0; j < 4; j++) sv[i][j] += ra[i] * rb[j];
        }

        // scale + mask + per-thread row max
        bool valid[4];
        #pragma unroll
        for (int j = 0; j < 4; j++) valid[j] = (s.kvalid[tx*4 + j] != 0.0f);
        #pragma unroll
        for (int i = 0; i < 4; i++) {
            float tm = -1e30f;
            #pragma unroll
            for (int j = 0; j < 4; j++) {
                float v = valid[j] ? sv[i][j] * SCALEF : -1e30f;
                sv[i][j] = v;
                tm = fmaxf(tm, v);
            }
            s.red[ty*4 + i][tx] = tm;
        }
        __syncthreads();

        // row max reduction + online-softmax rescale factor
        if (tid < 64) {
            float tm = -1e30f;
            #pragma unroll
            for (int t2 = 0; t2 < 16; t2++) tm = fmaxf(tm, s.red[tid][t2]);
            float m_new = fmaxf(s.row_m[tid], tm);
            s.row_scale[tid] = __expf(s.row_m[tid] - m_new);
            s.row_m[tid] = m_new;
        }
        __syncthreads();

        // P = exp(S - m), rescale O, partial row sums
        #pragma unroll
        for (int i = 0; i < 4; i++) {
            int q = ty*4 + i;
            float mq = s.row_m[q];
            float sc = s.row_scale[q];
            float ts = 0.0f;
            #pragma unroll
            for (int j = 0; j < 4; j++) {
                float p = valid[j] ? __expf(sv[i][j] - mq) : 0.0f;
                s.Ps[q][tx*4 + j] = p;
                ts += p;
                accO[i][j] *= sc;
            }
            s.red[q][tx] = ts;
        }
        __syncthreads();

        if (tid < 64) {
            float t2s = 0.0f;
            #pragma unroll
            for (int t2 = 0; t2 < 16; t2++) t2s += s.red[tid][t2];
            s.row_l[tid] = s.row_l[tid] * s.row_scale[tid] + t2s;
        }

        // O += P V (Ps/Vs stable until next top-of-loop sync)
        #pragma unroll 8
        for (int kk = 0; kk < 64; kk++) {
            float rp[4], rv[4];
            #pragma unroll
            for (int i = 0; i < 4; i++) rp[i] = s.Ps[ty*4 + i][kk];
            #pragma unroll
            for (int j = 0; j < 4; j++) rv[j] = s.Vs[kk][tx*4 + j];
            #pragma unroll
            for (int i = 0; i < 4; i++)
                #pragma unroll
                for (int j = 0; j < 4; j++) accO[i][j] += rp[i] * rv[j];
        }
    }
    __syncthreads();

    #pragma unroll
    for (int i = 0; i < 4; i++) {
        int q = q0 + ty*4 + i;
        float inv = 1.0f / s.row_l[ty*4 + i];
        float* dst = &g_ao[(size_t)(l*Nn + q) * INNER + h*DHd];
        #pragma unroll
        for (int j = 0; j < 4; j++) dst[tx*4 + j] = accO[i][j] * inv;
    }
}

// ---------------------------------------------------------------------------
// Output projection: out[m,o] = sum_e ao[m,e] * Wo[o,e] + bo[o]
// M=8192, K=512, Nout=1024
// ---------------------------------------------------------------------------
__global__ __launch_bounds__(256)
void oproj_kernel(const float* __restrict__ Wo,
                  const float* __restrict__ bo,
                  float* __restrict__ out) {
    __shared__ float As[16][65];
    __shared__ float Bs[16][65];

    const int m0 = blockIdx.y * 64;
    const int o0 = blockIdx.x * 64;
    const int tx = threadIdx.x, ty = threadIdx.y;
    const int tid = ty * 16 + tx;
    const int lr = tid >> 2;
    const int lk = (tid & 3) * 4;

    float acc[4][4] = {};

    for (int k0 = 0; k0 < INNER; k0 += 16) {
        float4 a = *(const float4*)&g_ao[(size_t)(m0 + lr) * INNER + k0 + lk];
        float4 b = *(const float4*)&Wo[(size_t)(o0 + lr) * INNER + k0 + lk];
        As[lk+0][lr] = a.x; As[lk+1][lr] = a.y; As[lk+2][lr] = a.z; As[lk+3][lr] = a.w;
        Bs[lk+0][lr] = b.x; Bs[lk+1][lr] = b.y; Bs[lk+2][lr] = b.z; Bs[lk+3][lr] = b.w;
        __syncthreads();
        #pragma unroll
        for (int kk = 0; kk < 16; kk++) {
            float ra[4], rb[4];
            #pragma unroll
            for (int i = 0; i < 4; i++) ra[i] = As[kk][ty*4 + i];
            #pragma unroll
            for (int j = 0; j < 4; j++) rb[j] = Bs[kk][tx*4 + j];
            #pragma unroll
            for (int i = 0; i < 4; i++)
                #pragma unroll
                for (int j = 0; j < 4; j++) acc[i][j] += ra[i] * rb[j];
        }
        __syncthreads();
    }

    #pragma unroll
    for (int i = 0; i < 4; i++) {
        int m = m0 + ty*4 + i;
        #pragma unroll
        for (int j = 0; j < 4; j++) {
            int o = o0 + tx*4 + j;
            out[(size_t)m * DOUT + o] = acc[i][j] + bo[o];
        }
    }
}

// ---------------------------------------------------------------------------
extern "C" void kernel_launch(void* const* d_in, const int* in_sizes, int n_in,
                              void* d_out, int out_size) {
    const float* x  = (const float*)d_in[0];
    const float* Wq = (const float*)d_in[1];
    const float* Wk = (const float*)d_in[2];
    const float* Wv = (const float*)d_in[3];
    const float* Wo = (const float*)d_in[4];
    const float* bo = (const float*)d_in[5];
    const unsigned char* mask = (const unsigned char*)d_in[6];
    float* out = (float*)d_out;

    mask_convert_kernel<<<1, 256>>>(mask);

    dim3 blk2d(16, 16);
    qkv_kernel<<<dim3(INNER/64, (Ld*Nn)/64, 3), blk2d>>>(x, Wq, Wk, Wv);

    cudaFuncSetAttribute(attn_kernel, cudaFuncAttributeMaxDynamicSharedMemorySize,
                         (int)sizeof(AttnSmem));
    attn_kernel<<<dim3(Nn/64, Hh, Ld), 256, sizeof(AttnSmem)>>>();

    oproj_kernel<<<dim3(DOUT/64, (Ld*Nn)/64), blk2d>>>(Wo, bo, out);
}

// round 3
// speedup vs baseline: 1.5993x; 1.5993x over previous
#include <cuda_runtime.h>
#include <cuda_bf16.h>
#include <math.h>
#include <cstdint>

// Problem constants
#define Ld 4
#define Nn 2048
#define DIN 1024
#define Hh 8
#define DHd 64
#define INNER 512
#define DOUT 1024
#define SCALEF 0.125f   // 64^-0.5

// Scratch (device globals; no allocations allowed)
__device__ float g_q[Ld*Hh*Nn*DHd];    // [L,H,N,DH]
__device__ float g_k[Ld*Hh*Nn*DHd];
__device__ float g_v[Ld*Hh*Nn*DHd];
__device__ float g_ao[Ld*Nn*INNER];    // [L,N,H*DH]
__device__ float g_mask[Ld*Nn];        // normalized 0/1 float

// ===========================================================================
// Mask dtype detection + normalization
// ===========================================================================
__global__ void mask_convert_kernel(const unsigned char* __restrict__ raw) {
    __shared__ int flag_float, flag_big;
    int tid = threadIdx.x;
    if (tid == 0) { flag_float = 0; flag_big = 0; }
    __syncthreads();
    const unsigned int* w = (const unsigned int*)raw;
    for (int i = tid; i < 2048; i += blockDim.x) {
        unsigned int v = w[i];
        if (v == 0x3F800000u) atomicOr(&flag_float, 1);
        else if (v > 1u)      atomicOr(&flag_big, 1);
    }
    __syncthreads();
    bool isfloat = (flag_float != 0);
    bool isbyte  = (!isfloat) && (flag_big != 0);
    for (int i = tid; i < Ld*Nn; i += blockDim.x) {
        unsigned int v;
        if (isbyte) v = raw[i];
        else        v = ((const unsigned int*)raw)[i];
        g_mask[i] = (v != 0u) ? 1.0f : 0.0f;
    }
}

// ===========================================================================
// mma.sync helpers (sm_80-class HMMA; legal on compute_103 without 'a')
// ===========================================================================
__device__ __forceinline__ void mma_bf16(float* c, const uint32_t* a, const uint32_t* b) {
    asm volatile(
        "mma.sync.aligned.m16n8k16.row.col.f32.bf16.bf16.f32 "
        "{%0,%1,%2,%3}, {%4,%5,%6,%7}, {%8,%9}, {%0,%1,%2,%3};"
        : "+f"(c[0]), "+f"(c[1]), "+f"(c[2]), "+f"(c[3])
        : "r"(a[0]), "r"(a[1]), "r"(a[2]), "r"(a[3]), "r"(b[0]), "r"(b[1]));
}

// Split an fp32 float4 into bf16 hi/lo pairs and store (packed bf16x2)
__device__ __forceinline__ void cvt_split_store(__nv_bfloat16* hi, __nv_bfloat16* lo,
                                                int eoff, float4 v) {
    __nv_bfloat16 h0 = __float2bfloat16_rn(v.x);
    __nv_bfloat16 h1 = __float2bfloat16_rn(v.y);
    __nv_bfloat16 h2 = __float2bfloat16_rn(v.z);
    __nv_bfloat16 h3 = __float2bfloat16_rn(v.w);
    __nv_bfloat16 l0 = __float2bfloat16_rn(v.x - __bfloat162float(h0));
    __nv_bfloat16 l1 = __float2bfloat16_rn(v.y - __bfloat162float(h1));
    __nv_bfloat16 l2 = __float2bfloat16_rn(v.z - __bfloat162float(h2));
    __nv_bfloat16 l3 = __float2bfloat16_rn(v.w - __bfloat162float(h3));
    *reinterpret_cast<__nv_bfloat162*>(hi + eoff)     = __halves2bfloat162(h0, h1);
    *reinterpret_cast<__nv_bfloat162*>(hi + eoff + 2) = __halves2bfloat162(h2, h3);
    *reinterpret_cast<__nv_bfloat162*>(lo + eoff)     = __halves2bfloat162(l0, l1);
    *reinterpret_cast<__nv_bfloat162*>(lo + eoff + 2) = __halves2bfloat162(l2, l3);
}

// ===========================================================================
// Tensor-core GEMM: C[128 x 64] = A[128 x K] * B[64 x K]^T  (fp32 in/out)
// 256 threads = 8 warps (4 m x 2 n), each warp 32x32 output.
// 3-term bf16 split: A_hi*B_hi + A_hi*B_lo + A_lo*B_hi, fp32 accumulate.
// ===========================================================================
#define BK 64
#define APAD_STRIDE 72          // bf16 elements per row (64 + 8 pad)
#define SM_A_HI 0
#define SM_A_LO (128 * APAD_STRIDE)
#define SM_B_HI (2 * 128 * APAD_STRIDE)
#define SM_B_LO (2 * 128 * APAD_STRIDE + 64 * APAD_STRIDE)
#define SM_GEMM_ELEMS (2 * 128 * APAD_STRIDE + 2 * 64 * APAD_STRIDE)
#define SM_GEMM_BYTES (SM_GEMM_ELEMS * 2)

struct CFrag { float c[2][4][4]; };   // [mtile][ntile][4]

__device__ __forceinline__ void gemm_tc_main(const float* __restrict__ A, int lda,
                                             const float* __restrict__ B, int ldb,
                                             int Kdim, __nv_bfloat16* sm, CFrag& f) {
    const int tid = threadIdx.x;
    const int wid = tid >> 5, lane = tid & 31;
    const int gid = lane >> 2, tig = lane & 3;
    const int warp_m = wid >> 1;    // 0..3
    const int warp_n = wid & 1;     // 0..1

    __nv_bfloat16* As_hi = sm + SM_A_HI;
    __nv_bfloat16* As_lo = sm + SM_A_LO;
    __nv_bfloat16* Bs_hi = sm + SM_B_HI;
    __nv_bfloat16* Bs_lo = sm + SM_B_LO;

    #pragma unroll
    for (int mt = 0; mt < 2; mt++)
        #pragma unroll
        for (int nt = 0; nt < 4; nt++)
            #pragma unroll
            for (int i = 0; i < 4; i++) f.c[mt][nt][i] = 0.0f;

    for (int k0 = 0; k0 < Kdim; k0 += BK) {
        // Load + split A tile (128 x 64): 2048 float4, 8 per thread
        #pragma unroll
        for (int it = 0; it < 8; it++) {
            int t = tid + it * 256;
            int r = t >> 4, c4 = (t & 15) << 2;
            float4 v = *(const float4*)(A + (size_t)r * lda + k0 + c4);
            cvt_split_store(As_hi, As_lo, r * APAD_STRIDE + c4, v);
        }
        // Load + split B tile (64 x 64): 1024 float4, 4 per thread
        #pragma unroll
        for (int it = 0; it < 4; it++) {
            int t = tid + it * 256;
            int r = t >> 4, c4 = (t & 15) << 2;
            float4 v = *(const float4*)(B + (size_t)r * ldb + k0 + c4);
            cvt_split_store(Bs_hi, Bs_lo, r * APAD_STRIDE + c4, v);
        }
        __syncthreads();

        #pragma unroll
        for (int ks = 0; ks < BK / 16; ks++) {
            const int kk = ks * 16 + tig * 2;
            uint32_t ah[2][4], al[2][4], bh[4][2], bl[4][2];
            #pragma unroll
            for (int mt = 0; mt < 2; mt++) {
                int r0 = warp_m * 32 + mt * 16 + gid;
                const uint32_t* ph = (const uint32_t*)(As_hi + r0 * APAD_STRIDE + kk);
                const uint32_t* ph8 = (const uint32_t*)(As_hi + (r0 + 8) * APAD_STRIDE + kk);
                const uint32_t* pl = (const uint32_t*)(As_lo + r0 * APAD_STRIDE + kk);
                const uint32_t* pl8 = (const uint32_t*)(As_lo + (r0 + 8) * APAD_STRIDE + kk);
                ah[mt][0] = ph[0];  ah[mt][1] = ph8[0];
                ah[mt][2] = ph[4];  ah[mt][3] = ph8[4];   // +8 bf16 = +4 u32
                al[mt][0] = pl[0];  al[mt][1] = pl8[0];
                al[mt][2] = pl[4];  al[mt][3] = pl8[4];
            }
            #pragma unroll
            for (int nt = 0; nt < 4; nt++) {
                int n0 = warp_n * 32 + nt * 8 + gid;
                const uint32_t* ph = (const uint32_t*)(Bs_hi + n0 * APAD_STRIDE + kk);
                const uint32_t* pl = (const uint32_t*)(Bs_lo + n0 * APAD_STRIDE + kk);
                bh[nt][0] = ph[0];  bh[nt][1] = ph[4];
                bl[nt][0] = pl[0];  bl[nt][1] = pl[4];
            }
            #pragma unroll
            for (int mt = 0; mt < 2; mt++)
                #pragma unroll
                for (int nt = 0; nt < 4; nt++) {
                    mma_bf16(f.c[mt][nt], ah[mt], bh[nt]);
                    mma_bf16(f.c[mt][nt], ah[mt], bl[nt]);
                    mma_bf16(f.c[mt][nt], al[mt], bh[nt]);
                }
        }
        __syncthreads();
    }
}

// ---------------------------------------------------------------------------
// QKV projection: grid (8 heads, 64 m-tiles, 3 matrices)
// ---------------------------------------------------------------------------
__global__ __launch_bounds__(256)
void qkv_tc_kernel(const float* __restrict__ x,
                   const float* __restrict__ Wq,
                   const float* __restrict__ Wk,
                   const float* __restrict__ Wv) {
    extern __shared__ __nv_bfloat16 smg[];
    const int which = blockIdx.z;
    const float* __restrict__ W = (which == 0) ? Wq : ((which == 1) ? Wk : Wv);
    float* __restrict__ outb    = (which == 0) ? g_q : ((which == 1) ? g_k : g_v);

    const int m0 = blockIdx.y * 128;
    const int e0 = blockIdx.x * 64;
    const int h  = blockIdx.x;

    CFrag f;
    gemm_tc_main(x + (size_t)m0 * DIN, DIN, W + (size_t)e0 * DIN, DIN, DIN, smg, f);

    const int tid = threadIdx.x;
    const int wid = tid >> 5, lane = tid & 31;
    const int gid = lane >> 2, tig = lane & 3;
    const int warp_m = wid >> 1, warp_n = wid & 1;

    #pragma unroll
    for (int mt = 0; mt < 2; mt++) {
        #pragma unroll
        for (int rr = 0; rr < 2; rr++) {
            int m = m0 + warp_m * 32 + mt * 16 + gid + rr * 8;
            int l = m >> 11, n = m & 2047;
            float* dst = outb + ((size_t)((l * Hh + h) * Nn + n)) * DHd;
            #pragma unroll
            for (int nt = 0; nt < 4; nt++) {
                int col = warp_n * 32 + nt * 8 + tig * 2;
                float2 v = make_float2(f.c[mt][nt][rr * 2], f.c[mt][nt][rr * 2 + 1]);
                *(float2*)(dst + col) = v;
            }
        }
    }
}

// ---------------------------------------------------------------------------
// Output projection: grid (16 o-tiles, 64 m-tiles)
// ---------------------------------------------------------------------------
__global__ __launch_bounds__(256)
void oproj_tc_kernel(const float* __restrict__ Wo,
                     const float* __restrict__ bo,
                     float* __restrict__ out) {
    extern __shared__ __nv_bfloat16 smg[];
    const int m0 = blockIdx.y * 128;
    const int o0 = blockIdx.x * 64;

    CFrag f;
    gemm_tc_main(g_ao + (size_t)m0 * INNER, INNER, Wo + (size_t)o0 * INNER, INNER,
                 INNER, smg, f);

    const int tid = threadIdx.x;
    const int wid = tid >> 5, lane = tid & 31;
    const int gid = lane >> 2, tig = lane & 3;
    const int warp_m = wid >> 1, warp_n = wid & 1;

    #pragma unroll
    for (int mt = 0; mt < 2; mt++) {
        #pragma unroll
        for (int rr = 0; rr < 2; rr++) {
            int m = m0 + warp_m * 32 + mt * 16 + gid + rr * 8;
            float* dst = out + (size_t)m * DOUT + o0;
            #pragma unroll
            for (int nt = 0; nt < 4; nt++) {
                int col = warp_n * 32 + nt * 8 + tig * 2;
                float2 b = *(const float2*)(bo + o0 + col);
                float2 v = make_float2(f.c[mt][nt][rr * 2] + b.x,
                                       f.c[mt][nt][rr * 2 + 1] + b.y);
                *(float2*)(dst + col) = v;
            }
        }
    }
}

// ---------------------------------------------------------------------------
// Flash attention per (l, h): SIMT fp32 (known correct from R1)
// ---------------------------------------------------------------------------
struct AttnSmem {
    float Qs[64][65];
    float Ks[64][65];
    float Vs[64][65];
    float Ps[64][65];
    float red[64][16];
    float row_m[64];
    float row_l[64];
    float row_scale[64];
    float kvalid[64];
};

__global__ __launch_bounds__(256)
void attn_kernel() {
    extern __shared__ char sbuf[];
    AttnSmem& s = *(AttnSmem*)sbuf;

    const int qb = blockIdx.x;
    const int h  = blockIdx.y;
    const int l  = blockIdx.z;
    const int tid = threadIdx.x;
    const int tx = tid & 15, ty = tid >> 4;
    const int q0 = qb * 64;

    const float* __restrict__ Q = g_q + (size_t)((l*Hh + h) * Nn) * DHd;
    const float* __restrict__ K = g_k + (size_t)((l*Hh + h) * Nn) * DHd;
    const float* __restrict__ V = g_v + (size_t)((l*Hh + h) * Nn) * DHd;

    for (int t = tid; t < 64*16; t += 256) {
        int r = t >> 4, c4 = (t & 15) * 4;
        float4 v = *(const float4*)&Q[(size_t)(q0 + r) * DHd + c4];
        s.Qs[r][c4+0] = v.x; s.Qs[r][c4+1] = v.y; s.Qs[r][c4+2] = v.z; s.Qs[r][c4+3] = v.w;
    }
    if (tid < 64) { s.row_m[tid] = -1e30f; s.row_l[tid] = 0.0f; }

    float accO[4][4] = {};

    for (int kb = 0; kb < Nn/64; kb++) {
        __syncthreads();
        for (int t = tid; t < 64*16; t += 256) {
            int r = t >> 4, c4 = (t & 15) * 4;
            float4 kv = *(const float4*)&K[(size_t)(kb*64 + r) * DHd + c4];
            s.Ks[r][c4+0] = kv.x; s.Ks[r][c4+1] = kv.y; s.Ks[r][c4+2] = kv.z; s.Ks[r][c4+3] = kv.w;
            float4 vv = *(const float4*)&V[(size_t)(kb*64 + r) * DHd + c4];
            s.Vs[r][c4+0] = vv.x; s.Vs[r][c4+1] = vv.y; s.Vs[r][c4+2] = vv.z; s.Vs[r][c4+3] = vv.w;
        }
        if (tid < 64) s.kvalid[tid] = g_mask[l*Nn + kb*64 + tid];
        __syncthreads();

        float sv[4][4] = {};
        #pragma unroll 8
        for (int d = 0; d < DHd; d++) {
            float ra[4], rb[4];
            #pragma unroll
            for (int i = 0; i < 4; i++) ra[i] = s.Qs[ty*4 + i][d];
            #pragma unroll
            for (int j = 0; j < 4; j++) rb[j] = s.Ks[tx*4 + j][d];
            #pragma unroll
            for (int i = 0; i < 4; i++)
                #pragma unroll
                for (int j = 0; j < 4; j++) sv[i][j] += ra[i] * rb[j];
        }

        bool valid[4];
        #pragma unroll
        for (int j = 0; j < 4; j++) valid[j] = (s.kvalid[tx*4 + j] != 0.0f);
        #pragma unroll
        for (int i = 0; i < 4; i++) {
            float tm = -1e30f;
            #pragma unroll
            for (int j = 0; j < 4; j++) {
                float v = valid[j] ? sv[i][j] * SCALEF : -1e30f;
                sv[i][j] = v;
                tm = fmaxf(tm, v);
            }
            s.red[ty*4 + i][tx] = tm;
        }
        __syncthreads();

        if (tid < 64) {
            float tm = -1e30f;
            #pragma unroll
            for (int t2 = 0; t2 < 16; t2++) tm = fmaxf(tm, s.red[tid][t2]);
            float m_new = fmaxf(s.row_m[tid], tm);
            s.row_scale[tid] = __expf(s.row_m[tid] - m_new);
            s.row_m[tid] = m_new;
        }
        __syncthreads();

        #pragma unroll
        for (int i = 0; i < 4; i++) {
            int q = ty*4 + i;
            float mq = s.row_m[q];
            float sc = s.row_scale[q];
            float ts = 0.0f;
            #pragma unroll
            for (int j = 0; j < 4; j++) {
                float p = valid[j] ? __expf(sv[i][j] - mq) : 0.0f;
                s.Ps[q][tx*4 + j] = p;
                ts += p;
                accO[i][j] *= sc;
            }
            s.red[q][tx] = ts;
        }
        __syncthreads();

        if (tid < 64) {
            float t2s = 0.0f;
            #pragma unroll
            for (int t2 = 0; t2 < 16; t2++) t2s += s.red[tid][t2];
            s.row_l[tid] = s.row_l[tid] * s.row_scale[tid] + t2s;
        }

        #pragma unroll 8
        for (int kk = 0; kk < 64; kk++) {
            float rp[4], rv[4];
            #pragma unroll
            for (int i = 0; i < 4; i++) rp[i] = s.Ps[ty*4 + i][kk];
            #pragma unroll
            for (int j = 0; j < 4; j++) rv[j] = s.Vs[kk][tx*4 + j];
            #pragma unroll
            for (int i = 0; i < 4; i++)
                #pragma unroll
                for (int j = 0; j < 4; j++) accO[i][j] += rp[i] * rv[j];
        }
    }
    __syncthreads();

    #pragma unroll
    for (int i = 0; i < 4; i++) {
        int q = q0 + ty*4 + i;
        float inv = 1.0f / s.row_l[ty*4 + i];
        float* dst = &g_ao[(size_t)(l*Nn + q) * INNER + h*DHd];
        #pragma unroll
        for (int j = 0; j < 4; j++) dst[tx*4 + j] = accO[i][j] * inv;
    }
}

// ---------------------------------------------------------------------------
extern "C" void kernel_launch(void* const* d_in, const int* in_sizes, int n_in,
                              void* d_out, int out_size) {
    const float* x  = (const float*)d_in[0];
    const float* Wq = (const float*)d_in[1];
    const float* Wk = (const float*)d_in[2];
    const float* Wv = (const float*)d_in[3];
    const float* Wo = (const float*)d_in[4];
    const float* bo = (const float*)d_in[5];
    const unsigned char* mask = (const unsigned char*)d_in[6];
    float* out = (float*)d_out;

    mask_convert_kernel<<<1, 256>>>(mask);

    cudaFuncSetAttribute(qkv_tc_kernel, cudaFuncAttributeMaxDynamicSharedMemorySize,
                         SM_GEMM_BYTES);
    cudaFuncSetAttribute(oproj_tc_kernel, cudaFuncAttributeMaxDynamicSharedMemorySize,
                         SM_GEMM_BYTES);

    qkv_tc_kernel<<<dim3(INNER/64, (Ld*Nn)/128, 3), 256, SM_GEMM_BYTES>>>(x, Wq, Wk, Wv);

    cudaFuncSetAttribute(attn_kernel, cudaFuncAttributeMaxDynamicSharedMemorySize,
                         (int)sizeof(AttnSmem));
    attn_kernel<<<dim3(Nn/64, Hh, Ld), 256, sizeof(AttnSmem)>>>();

    oproj_tc_kernel<<<dim3(DOUT/64, (Ld*Nn)/128), 256, SM_GEMM_BYTES>>>(Wo, bo, out);
}

// round 5
// speedup vs baseline: 3.3978x; 2.1246x over previous
#include <cuda_runtime.h>
#include <cuda_bf16.h>
#include <math.h>
#include <cstdint>

// Problem constants
#define Ld 4
#define Nn 2048
#define DIN 1024
#define Hh 8
#define DHd 64
#define INNER 512
#define DOUT 1024
#define SCALEF 0.125f   // 64^-0.5

// Scratch (device globals; no allocations allowed)
__device__ float g_q[Ld*Hh*Nn*DHd];    // [L,H,N,DH]
__device__ float g_k[Ld*Hh*Nn*DHd];
__device__ float g_v[Ld*Hh*Nn*DHd];
__device__ float g_ao[Ld*Nn*INNER];    // [L,N,H*DH]
__device__ float g_mask[Ld*Nn];        // normalized 0/1 float

// ===========================================================================
// Mask dtype detection + normalization
// ===========================================================================
__global__ void mask_convert_kernel(const unsigned char* __restrict__ raw) {
    __shared__ int flag_float, flag_big;
    int tid = threadIdx.x;
    if (tid == 0) { flag_float = 0; flag_big = 0; }
    __syncthreads();
    const unsigned int* w = (const unsigned int*)raw;
    for (int i = tid; i < 2048; i += blockDim.x) {
        unsigned int v = w[i];
        if (v == 0x3F800000u) atomicOr(&flag_float, 1);
        else if (v > 1u)      atomicOr(&flag_big, 1);
    }
    __syncthreads();
    bool isfloat = (flag_float != 0);
    bool isbyte  = (!isfloat) && (flag_big != 0);
    for (int i = tid; i < Ld*Nn; i += blockDim.x) {
        unsigned int v;
        if (isbyte) v = raw[i];
        else        v = ((const unsigned int*)raw)[i];
        g_mask[i] = (v != 0u) ? 1.0f : 0.0f;
    }
}

// ===========================================================================
// mma.sync helpers
// ===========================================================================
__device__ __forceinline__ void mma_bf16(float* c, const uint32_t* a, const uint32_t* b) {
    asm volatile(
        "mma.sync.aligned.m16n8k16.row.col.f32.bf16.bf16.f32 "
        "{%0,%1,%2,%3}, {%4,%5,%6,%7}, {%8,%9}, {%0,%1,%2,%3};"
        : "+f"(c[0]), "+f"(c[1]), "+f"(c[2]), "+f"(c[3])
        : "r"(a[0]), "r"(a[1]), "r"(a[2]), "r"(a[3]), "r"(b[0]), "r"(b[1]));
}

#define LDMX4T(r, a) \
    asm volatile("ldmatrix.sync.aligned.m8n8.x4.trans.shared.b16 {%0,%1,%2,%3}, [%4];" \
        : "=r"((r)[0]), "=r"((r)[1]), "=r"((r)[2]), "=r"((r)[3]) : "r"(a))

__device__ __forceinline__ uint32_t smem_to_u32(const void* p) {
    uint32_t a;
    asm("{ .reg .u64 t; cvta.to.shared.u64 t, %1; cvt.u32.u64 %0, t; }" : "=r"(a) : "l"(p));
    return a;
}

__device__ __forceinline__ uint32_t packbf2(float x, float y) {
    __nv_bfloat162 h = __floats2bfloat162_rn(x, y);
    return *reinterpret_cast<uint32_t*>(&h);
}

// Split an fp32 float4 into bf16 hi/lo pairs and store (packed bf16x2)
__device__ __forceinline__ void cvt_split_store(__nv_bfloat16* hi, __nv_bfloat16* lo,
                                                int eoff, float4 v) {
    __nv_bfloat16 h0 = __float2bfloat16_rn(v.x);
    __nv_bfloat16 h1 = __float2bfloat16_rn(v.y);
    __nv_bfloat16 h2 = __float2bfloat16_rn(v.z);
    __nv_bfloat16 h3 = __float2bfloat16_rn(v.w);
    __nv_bfloat16 l0 = __float2bfloat16_rn(v.x - __bfloat162float(h0));
    __nv_bfloat16 l1 = __float2bfloat16_rn(v.y - __bfloat162float(h1));
    __nv_bfloat16 l2 = __float2bfloat16_rn(v.z - __bfloat162float(h2));
    __nv_bfloat16 l3 = __float2bfloat16_rn(v.w - __bfloat162float(h3));
    *reinterpret_cast<__nv_bfloat162*>(hi + eoff)     = __halves2bfloat162(h0, h1);
    *reinterpret_cast<__nv_bfloat162*>(hi + eoff + 2) = __halves2bfloat162(h2, h3);
    *reinterpret_cast<__nv_bfloat162*>(lo + eoff)     = __halves2bfloat162(l0, l1);
    *reinterpret_cast<__nv_bfloat162*>(lo + eoff + 2) = __halves2bfloat162(l2, l3);
}

// Fast exp on the FMA pipe: exp(x) = 2^(x*log2e), degree-6 Taylor for 2^r,
// r in [-0.5, 0.5]. No MUFU. Handles x <= 0 (incl. -1e9 mask bias) via clamp.
__device__ __forceinline__ float fast_exp(float x) {
    float t = fmaxf(x * 1.4426950408889634f, -126.0f);
    int ni = __float2int_rn(t);
    float r = t - (float)ni;
    float p = 1.5403530e-4f;
    p = fmaf(p, r, 1.3333558e-3f);
    p = fmaf(p, r, 9.6181291e-3f);
    p = fmaf(p, r, 5.5504109e-2f);
    p = fmaf(p, r, 2.4022651e-1f);
    p = fmaf(p, r, 6.9314718e-1f);
    p = fmaf(p, r, 1.0f);
    return __int_as_float(__float_as_int(p) + (ni << 23));
}

// ===========================================================================
// Tensor-core GEMM: C[128 x 64] = A[128 x K] * B[64 x K]^T  (fp32 in/out)
// (validated in R3 — unchanged)
// ===========================================================================
#define BK 64
#define APAD_STRIDE 72
#define SM_A_HI 0
#define SM_A_LO (128 * APAD_STRIDE)
#define SM_B_HI (2 * 128 * APAD_STRIDE)
#define SM_B_LO (2 * 128 * APAD_STRIDE + 64 * APAD_STRIDE)
#define SM_GEMM_ELEMS (2 * 128 * APAD_STRIDE + 2 * 64 * APAD_STRIDE)
#define SM_GEMM_BYTES (SM_GEMM_ELEMS * 2)

struct CFrag { float c[2][4][4]; };

__device__ __forceinline__ void gemm_tc_main(const float* __restrict__ A, int lda,
                                             const float* __restrict__ B, int ldb,
                                             int Kdim, __nv_bfloat16* sm, CFrag& f) {
    const int tid = threadIdx.x;
    const int wid = tid >> 5, lane = tid & 31;
    const int gid = lane >> 2, tig = lane & 3;
    const int warp_m = wid >> 1;
    const int warp_n = wid & 1;

    __nv_bfloat16* As_hi = sm + SM_A_HI;
    __nv_bfloat16* As_lo = sm + SM_A_LO;
    __nv_bfloat16* Bs_hi = sm + SM_B_HI;
    __nv_bfloat16* Bs_lo = sm + SM_B_LO;

    #pragma unroll
    for (int mt = 0; mt < 2; mt++)
        #pragma unroll
        for (int nt = 0; nt < 4; nt++)
            #pragma unroll
            for (int i = 0; i < 4; i++) f.c[mt][nt][i] = 0.0f;

    for (int k0 = 0; k0 < Kdim; k0 += BK) {
        #pragma unroll
        for (int it = 0; it < 8; it++) {
            int t = tid + it * 256;
            int r = t >> 4, c4 = (t & 15) << 2;
            float4 v = *(const float4*)(A + (size_t)r * lda + k0 + c4);
            cvt_split_store(As_hi, As_lo, r * APAD_STRIDE + c4, v);
        }
        #pragma unroll
        for (int it = 0; it < 4; it++) {
            int t = tid + it * 256;
            int r = t >> 4, c4 = (t & 15) << 2;
            float4 v = *(const float4*)(B + (size_t)r * ldb + k0 + c4);
            cvt_split_store(Bs_hi, Bs_lo, r * APAD_STRIDE + c4, v);
        }
        __syncthreads();

        #pragma unroll
        for (int ks = 0; ks < BK / 16; ks++) {
            const int kk = ks * 16 + tig * 2;
            uint32_t ah[2][4], al[2][4], bh[4][2], bl[4][2];
            #pragma unroll
            for (int mt = 0; mt < 2; mt++) {
                int r0 = warp_m * 32 + mt * 16 + gid;
                const uint32_t* ph = (const uint32_t*)(As_hi + r0 * APAD_STRIDE + kk);
                const uint32_t* ph8 = (const uint32_t*)(As_hi + (r0 + 8) * APAD_STRIDE + kk);
                const uint32_t* pl = (const uint32_t*)(As_lo + r0 * APAD_STRIDE + kk);
                const uint32_t* pl8 = (const uint32_t*)(As_lo + (r0 + 8) * APAD_STRIDE + kk);
                ah[mt][0] = ph[0];  ah[mt][1] = ph8[0];
                ah[mt][2] = ph[4];  ah[mt][3] = ph8[4];
                al[mt][0] = pl[0];  al[mt][1] = pl8[0];
                al[mt][2] = pl[4];  al[mt][3] = pl8[4];
            }
            #pragma unroll
            for (int nt = 0; nt < 4; nt++) {
                int n0 = warp_n * 32 + nt * 8 + gid;
                const uint32_t* ph = (const uint32_t*)(Bs_hi + n0 * APAD_STRIDE + kk);
                const uint32_t* pl = (const uint32_t*)(Bs_lo + n0 * APAD_STRIDE + kk);
                bh[nt][0] = ph[0];  bh[nt][1] = ph[4];
                bl[nt][0] = pl[0];  bl[nt][1] = pl[4];
            }
            #pragma unroll
            for (int mt = 0; mt < 2; mt++)
                #pragma unroll
                for (int nt = 0; nt < 4; nt++) {
                    mma_bf16(f.c[mt][nt], ah[mt], bh[nt]);
                    mma_bf16(f.c[mt][nt], ah[mt], bl[nt]);
                    mma_bf16(f.c[mt][nt], al[mt], bh[nt]);
                }
        }
        __syncthreads();
    }
}

// ---------------------------------------------------------------------------
// QKV projection: grid (8 heads, 64 m-tiles, 3 matrices)
// ---------------------------------------------------------------------------
__global__ __launch_bounds__(256)
void qkv_tc_kernel(const float* __restrict__ x,
                   const float* __restrict__ Wq,
                   const float* __restrict__ Wk,
                   const float* __restrict__ Wv) {
    extern __shared__ __nv_bfloat16 smg[];
    const int which = blockIdx.z;
    const float* __restrict__ W = (which == 0) ? Wq : ((which == 1) ? Wk : Wv);
    float* __restrict__ outb    = (which == 0) ? g_q : ((which == 1) ? g_k : g_v);

    const int m0 = blockIdx.y * 128;
    const int e0 = blockIdx.x * 64;
    const int h  = blockIdx.x;

    CFrag f;
    gemm_tc_main(x + (size_t)m0 * DIN, DIN, W + (size_t)e0 * DIN, DIN, DIN, smg, f);

    const int tid = threadIdx.x;
    const int wid = tid >> 5, lane = tid & 31;
    const int gid = lane >> 2, tig = lane & 3;
    const int warp_m = wid >> 1, warp_n = wid & 1;

    #pragma unroll
    for (int mt = 0; mt < 2; mt++) {
        #pragma unroll
        for (int rr = 0; rr < 2; rr++) {
            int m = m0 + warp_m * 32 + mt * 16 + gid + rr * 8;
            int l = m >> 11, n = m & 2047;
            float* dst = outb + ((size_t)((l * Hh + h) * Nn + n)) * DHd;
            #pragma unroll
            for (int nt = 0; nt < 4; nt++) {
                int col = warp_n * 32 + nt * 8 + tig * 2;
                float2 v = make_float2(f.c[mt][nt][rr * 2], f.c[mt][nt][rr * 2 + 1]);
                *(float2*)(dst + col) = v;
            }
        }
    }
}

// ---------------------------------------------------------------------------
// Output projection: grid (16 o-tiles, 64 m-tiles)
// ---------------------------------------------------------------------------
__global__ __launch_bounds__(256)
void oproj_tc_kernel(const float* __restrict__ Wo,
                     const float* __restrict__ bo,
                     float* __restrict__ out) {
    extern __shared__ __nv_bfloat16 smg[];
    const int m0 = blockIdx.y * 128;
    const int o0 = blockIdx.x * 64;

    CFrag f;
    gemm_tc_main(g_ao + (size_t)m0 * INNER, INNER, Wo + (size_t)o0 * INNER, INNER,
                 INNER, smg, f);

    const int tid = threadIdx.x;
    const int wid = tid >> 5, lane = tid & 31;
    const int gid = lane >> 2, tig = lane & 3;
    const int warp_m = wid >> 1, warp_n = wid & 1;

    #pragma unroll
    for (int mt = 0; mt < 2; mt++) {
        #pragma unroll
        for (int rr = 0; rr < 2; rr++) {
            int m = m0 + warp_m * 32 + mt * 16 + gid + rr * 8;
            float* dst = out + (size_t)m * DOUT + o0;
            #pragma unroll
            for (int nt = 0; nt < 4; nt++) {
                int col = warp_n * 32 + nt * 8 + tig * 2;
                float2 b = *(const float2*)(bo + o0 + col);
                float2 v = make_float2(f.c[mt][nt][rr * 2] + b.x,
                                       f.c[mt][nt][rr * 2 + 1] + b.y);
                *(float2*)(dst + col) = v;
            }
        }
    }
}

// ===========================================================================
// Flash attention on HMMA. Per CTA: 64 q-rows, 4 warps (16 rows each),
// k-tiles of 64 keys, online softmax in registers, fast_exp on FMA pipe.
// bf16 hi/lo split on QK^T and PV (3 MMAs per logical MMA).
// ===========================================================================
#define ATS 72
// smem element offsets (bf16 units)
#define A_QH 0
#define A_QL 4608
#define A_KH 9216
#define A_KL 13824
#define A_VH 18432
#define A_VL 23040
#define A_BIAS_BYTES 55296
#define A_SMEM_BYTES  55552

__global__ __launch_bounds__(128, 3)
void attn_mma_kernel() {
    extern __shared__ char sb[];
    __nv_bfloat16* Qh = (__nv_bfloat16*)sb;
    __nv_bfloat16* Ql = Qh + A_QL;
    __nv_bfloat16* Kh = Qh + A_KH;
    __nv_bfloat16* Kl = Qh + A_KL;
    __nv_bfloat16* Vh = Qh + A_VH;
    __nv_bfloat16* Vl = Qh + A_VL;
    float* bias = (float*)(sb + A_BIAS_BYTES);

    const int qb = blockIdx.x, h = blockIdx.y, l = blockIdx.z;
    const int tid = threadIdx.x;
    const int wid = tid >> 5, lane = tid & 31;
    const int gid = lane >> 2, tig = lane & 3;
    const int q0 = qb * 64;

    const float* __restrict__ Qg = g_q + (size_t)((l*Hh + h) * Nn) * DHd;
    const float* __restrict__ Kg = g_k + (size_t)((l*Hh + h) * Nn) * DHd;
    const float* __restrict__ Vg = g_v + (size_t)((l*Hh + h) * Nn) * DHd;

    // Load Q (64x64), scale by SCALEF, split hi/lo
    #pragma unroll
    for (int it = 0; it < 8; it++) {
        int t = tid + it * 128;
        int r = t >> 4, c4 = (t & 15) << 2;
        float4 v = *(const float4*)(Qg + (size_t)(q0 + r) * DHd + c4);
        v.x *= SCALEF; v.y *= SCALEF; v.z *= SCALEF; v.w *= SCALEF;
        cvt_split_store(Qh, Ql, r * ATS + c4, v);
    }

    // ldmatrix address pattern for V (x4.trans): lane -> (row, col) offsets
    const int l4 = lane & 7, grp = lane >> 3;
    const int vrow = l4 + ((grp & 1) << 3);
    const int vcol = (grp >> 1) << 3;
    const uint32_t vh_base = smem_to_u32(Vh) + (uint32_t)(vrow * ATS + vcol) * 2;
    const uint32_t vl_base = smem_to_u32(Vl) + (uint32_t)(vrow * ATS + vcol) * 2;

    float o[8][4];
    #pragma unroll
    for (int nt = 0; nt < 8; nt++)
        #pragma unroll
        for (int i = 0; i < 4; i++) o[nt][i] = 0.0f;
    float m0 = -1e30f, m1 = -1e30f, l0 = 0.0f, l1 = 0.0f;

    for (int kb = 0; kb < Nn / 64; kb++) {
        __syncthreads();   // previous iteration's readers done
        // Load K, V tiles (64x64 each = 1024 float4 each), split hi/lo
        #pragma unroll
        for (int it = 0; it < 8; it++) {
            int t = tid + it * 128;
            int r = t >> 4, c4 = (t & 15) << 2;
            float4 kv = *(const float4*)(Kg + (size_t)(kb*64 + r) * DHd + c4);
            cvt_split_store(Kh, Kl, r * ATS + c4, kv);
            float4 vv = *(const float4*)(Vg + (size_t)(kb*64 + r) * DHd + c4);
            cvt_split_store(Vh, Vl, r * ATS + c4, vv);
        }
        if (tid < 64) bias[tid] = (g_mask[l*Nn + kb*64 + tid] - 1.0f) * 1e9f;
        __syncthreads();

        // ---- S = Q K^T (m16 x n64 per warp) ----
        float sfr[8][4];
        #pragma unroll
        for (int nt = 0; nt < 8; nt++)
            #pragma unroll
            for (int i = 0; i < 4; i++) sfr[nt][i] = 0.0f;

        #pragma unroll
        for (int ks = 0; ks < 4; ks++) {
            const int kk = ks * 16 + tig * 2;
            const __nv_bfloat16* qrh = Qh + (wid*16 + gid) * ATS + kk;
            const __nv_bfloat16* qrl = Ql + (wid*16 + gid) * ATS + kk;
            uint32_t ah[4], al[4];
            ah[0] = *(const uint32_t*)(qrh);
            ah[1] = *(const uint32_t*)(qrh + 8*ATS);
            ah[2] = *(const uint32_t*)(qrh + 8);
            ah[3] = *(const uint32_t*)(qrh + 8*ATS + 8);
            al[0] = *(const uint32_t*)(qrl);
            al[1] = *(const uint32_t*)(qrl + 8*ATS);
            al[2] = *(const uint32_t*)(qrl + 8);
            al[3] = *(const uint32_t*)(qrl + 8*ATS + 8);
            #pragma unroll
            for (int nt = 0; nt < 8; nt++) {
                const __nv_bfloat16* krh = Kh + (nt*8 + gid) * ATS + kk;
                const __nv_bfloat16* krl = Kl + (nt*8 + gid) * ATS + kk;
                uint32_t bh[2] = { *(const uint32_t*)krh, *(const uint32_t*)(krh + 8) };
                uint32_t bl[2] = { *(const uint32_t*)krl, *(const uint32_t*)(krl + 8) };
                mma_bf16(sfr[nt], ah, bh);
                mma_bf16(sfr[nt], ah, bl);
                mma_bf16(sfr[nt], al, bh);
            }
        }

        // ---- mask bias + row max ----
        float mx0 = -1e30f, mx1 = -1e30f;
        #pragma unroll
        for (int nt = 0; nt < 8; nt++) {
            float2 b2 = *(const float2*)(bias + nt*8 + tig*2);
            sfr[nt][0] += b2.x; sfr[nt][1] += b2.y;
            sfr[nt][2] += b2.x; sfr[nt][3] += b2.y;
            mx0 = fmaxf(mx0, fmaxf(sfr[nt][0], sfr[nt][1]));
            mx1 = fmaxf(mx1, fmaxf(sfr[nt][2], sfr[nt][3]));
        }
        mx0 = fmaxf(mx0, __shfl_xor_sync(0xFFFFFFFFu, mx0, 1));
        mx0 = fmaxf(mx0, __shfl_xor_sync(0xFFFFFFFFu, mx0, 2));
        mx1 = fmaxf(mx1, __shfl_xor_sync(0xFFFFFFFFu, mx1, 1));
        mx1 = fmaxf(mx1, __shfl_xor_sync(0xFFFFFFFFu, mx1, 2));

        float mn0 = fmaxf(m0, mx0), mn1 = fmaxf(m1, mx1);
        float sc0 = fast_exp(m0 - mn0), sc1 = fast_exp(m1 - mn1);
        m0 = mn0; m1 = mn1;

        // ---- P = exp(S - m); pack bf16 hi/lo A-fragments; row sums ----
        float rs0 = 0.0f, rs1 = 0.0f;
        uint32_t ph[8][2], pl[8][2];
        #pragma unroll
        for (int nt = 0; nt < 8; nt++) {
            float p0 = fast_exp(sfr[nt][0] - m0);
            float p1 = fast_exp(sfr[nt][1] - m0);
            float p2 = fast_exp(sfr[nt][2] - m1);
            float p3 = fast_exp(sfr[nt][3] - m1);
            rs0 += p0 + p1; rs1 += p2 + p3;
            __nv_bfloat16 h0 = __float2bfloat16_rn(p0);
            __nv_bfloat16 h1 = __float2bfloat16_rn(p1);
            __nv_bfloat16 h2 = __float2bfloat16_rn(p2);
            __nv_bfloat16 h3 = __float2bfloat16_rn(p3);
            ph[nt][0] = packbf2(__bfloat162float(h0), __bfloat162float(h1));
            ph[nt][1] = packbf2(__bfloat162float(h2), __bfloat162float(h3));
            pl[nt][0] = packbf2(p0 - __bfloat162float(h0), p1 - __bfloat162float(h1));
            pl[nt][1] = packbf2(p2 - __bfloat162float(h2), p3 - __bfloat162float(h3));
        }
        rs0 += __shfl_xor_sync(0xFFFFFFFFu, rs0, 1);
        rs0 += __shfl_xor_sync(0xFFFFFFFFu, rs0, 2);
        rs1 += __shfl_xor_sync(0xFFFFFFFFu, rs1, 1);
        rs1 += __shfl_xor_sync(0xFFFFFFFFu, rs1, 2);
        l0 = l0 * sc0 + rs0;
        l1 = l1 * sc1 + rs1;

        // ---- rescale O ----
        #pragma unroll
        for (int nt = 0; nt < 8; nt++) {
            o[nt][0] *= sc0; o[nt][1] *= sc0;
            o[nt][2] *= sc1; o[nt][3] *= sc1;
        }

        // ---- O += P V ----
        #pragma unroll
        for (int ks = 0; ks < 4; ks++) {
            uint32_t aph[4] = { ph[2*ks][0], ph[2*ks][1], ph[2*ks+1][0], ph[2*ks+1][1] };
            uint32_t apl[4] = { pl[2*ks][0], pl[2*ks][1], pl[2*ks+1][0], pl[2*ks+1][1] };
            #pragma unroll
            for (int dhc = 0; dhc < 4; dhc++) {
                uint32_t off = (uint32_t)(ks * 16 * ATS + dhc * 16) * 2;
                uint32_t bvh[4], bvl[4];
                LDMX4T(bvh, vh_base + off);
                LDMX4T(bvl, vl_base + off);
                int nt = dhc * 2;
                mma_bf16(o[nt],   aph, bvh);
                mma_bf16(o[nt],   aph, bvl);
                mma_bf16(o[nt],   apl, bvh);
                mma_bf16(o[nt+1], aph, bvh + 2);
                mma_bf16(o[nt+1], aph, bvl + 2);
                mma_bf16(o[nt+1], apl, bvh + 2);
            }
        }
    }

    // ---- epilogue: normalize and write [L,N,H*DH] ----
    float inv0 = 1.0f / l0, inv1 = 1.0f / l1;
    int qr0 = q0 + wid*16 + gid;
    float* d0 = g_ao + (size_t)(l*Nn + qr0) * INNER + h*DHd;
    float* d1 = g_ao + (size_t)(l*Nn + qr0 + 8) * INNER + h*DHd;
    #pragma unroll
    for (int nt = 0; nt < 8; nt++) {
        int col = nt*8 + tig*2;
        *(float2*)(d0 + col) = make_float2(o[nt][0]*inv0, o[nt][1]*inv0);
        *(float2*)(d1 + col) = make_float2(o[nt][2]*inv1, o[nt][3]*inv1);
    }
}

// ---------------------------------------------------------------------------
extern "C" void kernel_launch(void* const* d_in, const int* in_sizes, int n_in,
                              void* d_out, int out_size) {
    const float* x  = (const float*)d_in[0];
    const float* Wq = (const float*)d_in[1];
    const float* Wk = (const float*)d_in[2];
    const float* Wv = (const float*)d_in[3];
    const float* Wo = (const float*)d_in[4];
    const float* bo = (const float*)d_in[5];
    const unsigned char* mask = (const unsigned char*)d_in[6];
    float* out = (float*)d_out;

    mask_convert_kernel<<<1, 256>>>(mask);

    cudaFuncSetAttribute(qkv_tc_kernel, cudaFuncAttributeMaxDynamicSharedMemorySize,
                         SM_GEMM_BYTES);
    cudaFuncSetAttribute(oproj_tc_kernel, cudaFuncAttributeMaxDynamicSharedMemorySize,
                         SM_GEMM_BYTES);
    cudaFuncSetAttribute(attn_mma_kernel, cudaFuncAttributeMaxDynamicSharedMemorySize,
                         A_SMEM_BYTES);

    qkv_tc_kernel<<<dim3(INNER/64, (Ld*Nn)/128, 3), 256, SM_GEMM_BYTES>>>(x, Wq, Wk, Wv);

    attn_mma_kernel<<<dim3(Nn/64, Hh, Ld), 128, A_SMEM_BYTES>>>();

    oproj_tc_kernel<<<dim3(DOUT/64, (Ld*Nn)/128), 256, SM_GEMM_BYTES>>>(Wo, bo, out);
}